// round 16
// baseline (speedup 1.0000x reference)
#include <cuda_runtime.h>
#include <cuda_fp16.h>
#include <cstdint>

#define TT   4096
#define DD   2048
#define FF   2048
#define EE   8
#define CAP  4096

// ---------------- storage: fp16 activations + fp16 weights ----------
__device__ __half g_x16[(size_t)TT * DD];
__device__ __half g_sw13[(size_t)2 * FF * DD];
__device__ __half g_sw2[(size_t)DD * FF];
__device__ __half g_rw13[(size_t)EE * 2 * FF * DD];
__device__ __half g_rw2[(size_t)EE * DD * FF];
__device__ __half g_actsh[(size_t)TT * FF];
__device__ __half g_actrt[(size_t)EE * CAP * FF];
__device__ int   g_counts[EE];
__device__ int   g_tok[EE * CAP];
__device__ float g_gate[EE * CAP];

// ---------------- PTX helpers ----------------
__device__ __forceinline__ uint32_t smem_u32(const void* p) {
    uint32_t a;
    asm("{ .reg .u64 t; cvta.to.shared.u64 t, %1; cvt.u32.u64 %0, t; }" : "=r"(a) : "l"(p));
    return a;
}
#define CPA16(d, s) \
    asm volatile("cp.async.cg.shared.global [%0], [%1], 16;" :: "r"(d), "l"(s) : "memory")
#define CPA_COMMIT() asm volatile("cp.async.commit_group;" ::: "memory")
#define CPA_WAIT1()  asm volatile("cp.async.wait_group 1;" ::: "memory")

#define LDSM4(r0, r1, r2, r3, addr) \
    asm volatile("ldmatrix.sync.aligned.m8n8.x4.shared.b16 {%0,%1,%2,%3}, [%4];" \
                 : "=r"(r0), "=r"(r1), "=r"(r2), "=r"(r3) : "r"(addr))

#define MMA16816(d, a, b0v, b1v) \
    asm volatile("mma.sync.aligned.m16n8k16.row.col.f32.f16.f16.f32 " \
                 "{%0,%1,%2,%3}, {%4,%5,%6,%7}, {%8,%9}, {%0,%1,%2,%3};" \
                 : "+f"((d)[0]), "+f"((d)[1]), "+f"((d)[2]), "+f"((d)[3]) \
                 : "r"((a)[0]), "r"((a)[1]), "r"((a)[2]), "r"((a)[3]), \
                   "r"(b0v), "r"(b1v))

// smem: [tok 512][gate 512][3 stages x 32768 : A 16K | B 16K]
#define STAGE_SZ   32768
#define SM_STAGES  1024
#define SMEM_BYTES (SM_STAGES + 3 * STAGE_SZ)   // 99328

// ---------------- fp32 -> fp16, 8 floats per iteration ----------------
__device__ __forceinline__ void conv_range(const float4* __restrict__ src,
                                           uint4* __restrict__ dst,
                                           size_t n8, size_t gid, size_t nth)
{
#pragma unroll 2
    for (size_t i = gid; i < n8; i += nth) {
        float4 a = __ldcs(src + 2 * i);
        float4 b = __ldcs(src + 2 * i + 1);
        __half2 h0 = __floats2half2_rn(a.x, a.y);
        __half2 h1 = __floats2half2_rn(a.z, a.w);
        __half2 h2 = __floats2half2_rn(b.x, b.y);
        __half2 h3 = __floats2half2_rn(b.z, b.w);
        uint4 o;
        o.x = *reinterpret_cast<uint32_t*>(&h0);
        o.y = *reinterpret_cast<uint32_t*>(&h1);
        o.z = *reinterpret_cast<uint32_t*>(&h2);
        o.w = *reinterpret_cast<uint32_t*>(&h3);
        __stcs(dst + i, o);
    }
}

// ---------------- shared GEMM tile machinery (CTA 128x128, 4 warps) ---------
struct MMACtx {
    uint32_t sb;
    uint32_t wA[8], wB[8];
    uint32_t abase[4], axor[4], bbase[4], bxor[4];
    uint32_t hsel;
    int mw, nw, lane;
};

__device__ __forceinline__ void ctx_init(MMACtx& c, char* smem, int tid)
{
    const int lane = tid & 31, wid = tid >> 5;
    c.lane = lane;
    c.sb = smem_u32(smem) + SM_STAGES;
    const int lr = tid;
#pragma unroll
    for (int j = 0; j < 8; j++) {
        c.wA[j] = (uint32_t)(lr * 128 + ((j ^ (lr & 7)) << 4));
        c.wB[j] = (uint32_t)(16384 + lr * 128 + ((j ^ (lr & 7)) << 4));
    }
    c.mw = wid >> 1; c.nw = wid & 1;
#pragma unroll
    for (int mi = 0; mi < 4; mi++) {
        int ar = c.mw * 64 + mi * 16 + (lane & 15);
        c.abase[mi] = (uint32_t)(ar * 128);
        c.axor[mi]  = (uint32_t)(ar & 7);
    }
#pragma unroll
    for (int nj = 0; nj < 4; nj++) {
        int br = c.nw * 64 + nj * 16 + (lane & 15);
        c.bbase[nj] = (uint32_t)(16384 + br * 128);
        c.bxor[nj]  = (uint32_t)(br & 7);
    }
    c.hsel = (uint32_t)(lane >> 4);
}

__device__ __forceinline__ void gemm_loop(const MMACtx& c,
                                          const char* __restrict__ pA,
                                          const char* __restrict__ pB,
                                          float acc[4][8][4])
{
#pragma unroll
    for (int mi = 0; mi < 4; mi++)
#pragma unroll
        for (int nj = 0; nj < 8; nj++)
#pragma unroll
            for (int q = 0; q < 4; q++) acc[mi][nj][q] = 0.f;

    auto issue = [&](int cc) {
        const uint32_t st = c.sb + (cc % 3) * STAGE_SZ;
        const int kb = cc * 128;
#pragma unroll
        for (int j = 0; j < 8; j++) CPA16(st + c.wA[j], pA + kb + j * 16);
#pragma unroll
        for (int j = 0; j < 8; j++) CPA16(st + c.wB[j], pB + kb + j * 16);
        CPA_COMMIT();
    };

    issue(0);
    issue(1);

    for (int cc = 0; cc < 32; cc++) {
        CPA_WAIT1();
        __syncthreads();
        if (cc + 2 < 32) issue(cc + 2);
        const uint32_t st = c.sb + (cc % 3) * STAGE_SZ;
#pragma unroll
        for (int ks = 0; ks < 4; ks++) {
            uint32_t a[4][4], bf[4][4];
#pragma unroll
            for (int mi = 0; mi < 4; mi++)
                LDSM4(a[mi][0], a[mi][1], a[mi][2], a[mi][3],
                      st + c.abase[mi] + ((((uint32_t)ks * 2 + c.hsel) ^ c.axor[mi]) << 4));
#pragma unroll
            for (int nj = 0; nj < 4; nj++)
                LDSM4(bf[nj][0], bf[nj][1], bf[nj][2], bf[nj][3],
                      st + c.bbase[nj] + ((((uint32_t)ks * 2 + c.hsel) ^ c.bxor[nj]) << 4));
#pragma unroll
            for (int mi = 0; mi < 4; mi++)
#pragma unroll
                for (int nj = 0; nj < 4; nj++) {
                    MMA16816(acc[mi][nj * 2],     a[mi], bf[nj][0], bf[nj][2]);
                    MMA16816(acc[mi][nj * 2 + 1], a[mi], bf[nj][1], bf[nj][3]);
                }
        }
    }
}

// ---------------- tiny zero (counters only) ----------------
__global__ void zero_kernel() {
    if (threadIdx.x < EE) g_counts[threadIdx.x] = 0;
}

// ---------------- prep: conv x + conv sw13 (blocks<1536) + router (>=1536) --
__global__ void prep_kernel(const float* __restrict__ x,
                            const float* __restrict__ router,
                            const float* __restrict__ sw13,
                            uint4* __restrict__ dx, uint4* __restrict__ d13)
{
    if (blockIdx.x < 1536) {
        size_t gid = (size_t)blockIdx.x * blockDim.x + threadIdx.x;
        size_t nth = (size_t)1536 * blockDim.x;
        conv_range((const float4*)x, dx, (size_t)TT * DD / 8, gid, nth);
        conv_range((const float4*)sw13, d13, (size_t)2 * FF * DD / 8, gid, nth);
        return;
    }
    int warp = (int)(((blockIdx.x - 1536) * blockDim.x + threadIdx.x) >> 5);
    int lane = threadIdx.x & 31;
    if (warp >= TT) return;
    const float* xt = x + (size_t)warp * DD;
    float s[EE];
#pragma unroll
    for (int e = 0; e < EE; e++) s[e] = 0.f;
    for (int d = lane; d < DD; d += 32) {
        float xv = xt[d];
        const float* rr = router + (size_t)d * EE;
#pragma unroll
        for (int e = 0; e < EE; e++) s[e] += xv * rr[e];
    }
#pragma unroll
    for (int e = 0; e < EE; e++)
#pragma unroll
        for (int off = 16; off; off >>= 1)
            s[e] += __shfl_xor_sync(0xffffffffu, s[e], off);
    if (lane == 0) {
        float sc[EE];
#pragma unroll
        for (int e = 0; e < EE; e++) sc[e] = 1.f / (1.f + expf(-s[e]));
        int i1 = 0;
#pragma unroll
        for (int e = 1; e < EE; e++) if (sc[e] > sc[i1]) i1 = e;
        int i2 = (i1 == 0) ? 1 : 0;
#pragma unroll
        for (int e = 0; e < EE; e++)
            if (e != i1 && sc[e] > sc[i2]) i2 = e;
        int p1 = atomicAdd(&g_counts[i1], 1);
        g_tok[i1 * CAP + p1]  = warp;
        g_gate[i1 * CAP + p1] = sc[i1];
        int p2 = atomicAdd(&g_counts[i2], 1);
        g_tok[i2 * CAP + p2]  = warp;
        g_gate[i2 * CAP + p2] = sc[i2];
    }
}

// ---------------- launch 3: shared GEMM13 (z=0) + conv rw13,sw2 (z=1) -------
__global__ void __launch_bounds__(128, 2) moe_g13_shared(
    const __half* __restrict__ a16, const __half* __restrict__ b,
    __half* __restrict__ out_h,
    const float4* __restrict__ cv_s0, uint4* __restrict__ cv_d0, size_t cv_n0,
    const float4* __restrict__ cv_s1, uint4* __restrict__ cv_d1, size_t cv_n1)
{
    extern __shared__ char smem[];
    const int tid = threadIdx.x;

    if (blockIdx.z == 1) {
        size_t gid = ((size_t)blockIdx.y * gridDim.x + blockIdx.x) * blockDim.x + tid;
        size_t nth = (size_t)gridDim.x * gridDim.y * blockDim.x;
        conv_range(cv_s0, cv_d0, cv_n0, gid, nth);
        conv_range(cv_s1, cv_d1, cv_n1, gid, nth);
        return;
    }
    const int m0 = blockIdx.y * 128;
    MMACtx c; ctx_init(c, smem, tid);
    __syncthreads();

    const int lr = tid;
    const char* pA = (const char*)(a16 + (size_t)(m0 + lr) * 2048);
    size_t bRow = (size_t)((lr & 1) * 2048 + blockIdx.x * 64 + (lr >> 1));
    const char* pB = (const char*)(b + bRow * 2048);

    float acc[4][8][4];
    gemm_loop(c, pA, pB, acc);

    const int t4 = c.lane & 3;
#pragma unroll
    for (int mi = 0; mi < 4; mi++) {
        const int r0 = m0 + c.mw * 64 + mi * 16 + (c.lane >> 2);
        const int r1 = r0 + 8;
#pragma unroll
        for (int nj = 0; nj < 8; nj++) {
            const int actcol = blockIdx.x * 64 + c.nw * 32 + nj * 4 + t4;
            {
                float y0 = acc[mi][nj][0], y1 = acc[mi][nj][1];
                float v  = y0 / (1.f + expf(-y0)) * y1;
                out_h[(size_t)r0 * 2048 + actcol] = __float2half(v);
            }
            {
                float y0 = acc[mi][nj][2], y1 = acc[mi][nj][3];
                float v  = y0 / (1.f + expf(-y0)) * y1;
                out_h[(size_t)r1 * 2048 + actcol] = __float2half(v);
            }
        }
    }
}

// ---------------- launch 4: routed GEMM13 (z<8) + conv rw2 (z=8) +
//                  shared GEMM2 plain-store (z=9) ----------------------------
__global__ void __launch_bounds__(128, 2) moe_mid(
    const __half* __restrict__ x16, const __half* __restrict__ rw13,
    __half* __restrict__ actrt,
    const __half* __restrict__ actsh, const __half* __restrict__ sw2,
    float* __restrict__ out,
    const int* __restrict__ counts, const int* __restrict__ tok,
    const float* __restrict__ gate,
    const float4* __restrict__ cv_s, uint4* __restrict__ cv_d, size_t cv_n)
{
    extern __shared__ char smem[];
    const int tid = threadIdx.x;
    const int z = blockIdx.z;

    if (z == EE) {   // conv rw2
        size_t gid = ((size_t)blockIdx.y * gridDim.x + blockIdx.x) * blockDim.x + tid;
        size_t nth = (size_t)gridDim.x * gridDim.y * blockDim.x;
        conv_range(cv_s, cv_d, cv_n, gid, nth);
        return;
    }

    if (z == EE + 1) {   // shared GEMM2: out = actsh @ sw2^T (plain stores)
        if (blockIdx.x >= DD / 128) return;
        const int m0 = blockIdx.y * 128;
        MMACtx c; ctx_init(c, smem, tid);
        __syncthreads();
        const int lr = tid;
        const char* pA = (const char*)(actsh + (size_t)(m0 + lr) * 2048);
        const char* pB = (const char*)(sw2 + (size_t)(blockIdx.x * 128 + lr) * 2048);
        float acc[4][8][4];
        gemm_loop(c, pA, pB, acc);
        const int t4 = c.lane & 3;
#pragma unroll
        for (int mi = 0; mi < 4; mi++) {
            const int r0 = m0 + c.mw * 64 + mi * 16 + (c.lane >> 2);
            const int r1 = r0 + 8;
#pragma unroll
            for (int nj = 0; nj < 8; nj++) {
                const int col = blockIdx.x * 128 + c.nw * 64 + nj * 8 + t4 * 2;
                *(float2*)(out + (size_t)r0 * 2048 + col) =
                    make_float2(acc[mi][nj][0], acc[mi][nj][1]);
                *(float2*)(out + (size_t)r1 * 2048 + col) =
                    make_float2(acc[mi][nj][2], acc[mi][nj][3]);
            }
        }
        return;
    }

    // routed GEMM13 (gathered + gated)
    const int e   = z;
    const int cnt = counts[e];
    const int m0  = blockIdx.y * 128;
    if (m0 >= cnt) return;

    int*   tok_s  = (int*)smem;
    float* gate_s = (float*)(smem + 512);
    {
        int r = m0 + tid;
        tok_s[tid]  = (r < cnt) ? tok[e * CAP + r]  : 0;
        gate_s[tid] = (r < cnt) ? gate[e * CAP + r] : 0.f;
    }
    MMACtx c; ctx_init(c, smem, tid);
    __syncthreads();

    const int lr = tid;
    const char* pA = (const char*)(x16 + (size_t)tok_s[lr] * 2048);
    size_t bRow = (size_t)((lr & 1) * 2048 + blockIdx.x * 64 + (lr >> 1));
    const char* pB = (const char*)(rw13 + (size_t)e * (2 * FF * DD) + bRow * 2048);

    float acc[4][8][4];
    gemm_loop(c, pA, pB, acc);

    const int t4 = c.lane & 3;
#pragma unroll
    for (int mi = 0; mi < 4; mi++) {
        const int lr0 = c.mw * 64 + mi * 16 + (c.lane >> 2);
        const int lr1 = lr0 + 8;
        const int r0 = m0 + lr0, r1 = m0 + lr1;
        const float g0 = gate_s[lr0], g1 = gate_s[lr1];
#pragma unroll
        for (int nj = 0; nj < 8; nj++) {
            const int actcol = blockIdx.x * 64 + c.nw * 32 + nj * 4 + t4;
            if (r0 < cnt) {
                float y0 = g0 * acc[mi][nj][0], y1 = g0 * acc[mi][nj][1];
                float v  = y0 / (1.f + expf(-y0)) * y1;
                actrt[((size_t)e * CAP + r0) * 2048 + actcol] = __float2half(v);
            }
            if (r1 < cnt) {
                float y0 = g1 * acc[mi][nj][2], y1 = g1 * acc[mi][nj][3];
                float v  = y0 / (1.f + expf(-y0)) * y1;
                actrt[((size_t)e * CAP + r1) * 2048 + actcol] = __float2half(v);
            }
        }
    }
}

// ---------------- launch 5: routed GEMM2, atomicAdd scatter into out --------
__global__ void __launch_bounds__(128, 2) moe_gemm2r(
    const __half* __restrict__ actrt, const __half* __restrict__ rw2,
    float* __restrict__ out,
    const int* __restrict__ counts, const int* __restrict__ tok)
{
    extern __shared__ char smem[];
    const int tid = threadIdx.x;
    const int e   = blockIdx.z;
    const int cnt = counts[e];
    const int m0  = blockIdx.y * 128;
    if (m0 >= cnt) return;

    int* tok_s = (int*)smem;
    {
        int r = m0 + tid;
        tok_s[tid] = (r < cnt) ? tok[e * CAP + r] : 0;
    }
    MMACtx c; ctx_init(c, smem, tid);
    __syncthreads();

    const int lr = tid;
    const char* pA = (const char*)(actrt + ((size_t)e * CAP + (m0 + lr)) * 2048);
    const char* pB = (const char*)(rw2 + (size_t)e * DD * FF +
                                   (size_t)(blockIdx.x * 128 + lr) * 2048);

    float acc[4][8][4];
    gemm_loop(c, pA, pB, acc);

    const int t4 = c.lane & 3;
#pragma unroll
    for (int mi = 0; mi < 4; mi++) {
        const int lr0 = c.mw * 64 + mi * 16 + (c.lane >> 2);
        const int lr1 = lr0 + 8;
        const int r0 = m0 + lr0, r1 = m0 + lr1;
        const int to0 = tok_s[lr0], to1 = tok_s[lr1];
#pragma unroll
        for (int nj = 0; nj < 8; nj++) {
            const int col = blockIdx.x * 128 + c.nw * 64 + nj * 8 + t4 * 2;
            if (r0 < cnt) {
                float* p = out + (size_t)to0 * 2048 + col;
                atomicAdd(p,     acc[mi][nj][0]);
                atomicAdd(p + 1, acc[mi][nj][1]);
            }
            if (r1 < cnt) {
                float* p = out + (size_t)to1 * 2048 + col;
                atomicAdd(p,     acc[mi][nj][2]);
                atomicAdd(p + 1, acc[mi][nj][3]);
            }
        }
    }
}

// ---------------- launch ----------------
extern "C" void kernel_launch(void* const* d_in, const int* in_sizes, int n_in,
                              void* d_out, int out_size)
{
    const float* x    = (const float*)d_in[0];
    const float* rte  = (const float*)d_in[1];
    const float* sw13 = (const float*)d_in[2];
    const float* sw2  = (const float*)d_in[3];
    const float* rw13 = (const float*)d_in[4];
    const float* rw2  = (const float*)d_in[5];
    float* out = (float*)d_out;

    __half *x16, *s13, *s2, *r13, *r2, *ash, *art;
    float *gates;
    int *cnts, *toks;
    cudaGetSymbolAddress((void**)&x16, g_x16);
    cudaGetSymbolAddress((void**)&s13, g_sw13);
    cudaGetSymbolAddress((void**)&s2, g_sw2);
    cudaGetSymbolAddress((void**)&r13, g_rw13);
    cudaGetSymbolAddress((void**)&r2, g_rw2);
    cudaGetSymbolAddress((void**)&ash, g_actsh);
    cudaGetSymbolAddress((void**)&art, g_actrt);
    cudaGetSymbolAddress((void**)&cnts, g_counts);
    cudaGetSymbolAddress((void**)&toks, g_tok);
    cudaGetSymbolAddress((void**)&gates, g_gate);

    cudaFuncSetAttribute((const void*)moe_g13_shared,
                         cudaFuncAttributeMaxDynamicSharedMemorySize, SMEM_BYTES);
    cudaFuncSetAttribute((const void*)moe_mid,
                         cudaFuncAttributeMaxDynamicSharedMemorySize, SMEM_BYTES);
    cudaFuncSetAttribute((const void*)moe_gemm2r,
                         cudaFuncAttributeMaxDynamicSharedMemorySize, SMEM_BYTES);

    // 1) zero counters
    zero_kernel<<<1, 32>>>();

    // 2) prep: conv x + conv sw13 + router
    prep_kernel<<<1536 + 512, 256>>>(x, rte, sw13, (uint4*)x16, (uint4*)s13);

    // 3) shared GEMM13 (fused swiglu -> actsh) + hidden conv rw13,sw2
    moe_g13_shared<<<dim3(FF / 64, TT / 128, 2), 128, SMEM_BYTES>>>(
        x16, s13, ash,
        (const float4*)rw13, (uint4*)r13, (size_t)EE * 2 * FF * DD / 8,
        (const float4*)sw2,  (uint4*)s2,  (size_t)DD * FF / 8);

    // 4) routed GEMM13 + hidden conv rw2 + shared GEMM2 (plain store into out)
    moe_mid<<<dim3(FF / 64, CAP / 128, EE + 2), 128, SMEM_BYTES>>>(
        x16, r13, art, ash, s2, out, cnts, toks, gates,
        (const float4*)rw2, (uint4*)r2, (size_t)EE * DD * FF / 8);

    // 5) routed GEMM2, atomicAdd into out
    moe_gemm2r<<<dim3(DD / 128, TT / 128, EE), 128, SMEM_BYTES>>>(
        art, r2, out, cnts, toks);
}